// round 5
// baseline (speedup 1.0000x reference)
#include <cuda_runtime.h>
#include <math.h>
#include <stdint.h>
#include <stddef.h>

#define Bv   1024
#define Tv   256
#define EH   256
#define DH   512
#define ZL   128
#define PTc  5
#define OUTC 123
#define NTHR 256

// ---------------- device scratch ----------------
__device__ float d_WhhF[4*EH*EH];     // encoder recurrent, gate-interleaved, tf32-rounded
__device__ float d_WihF[4*EH*PTc];    // encoder stroke input, interleaved (fp32 exact)
__device__ float d_bF[4*EH];          // encoder bias, interleaved
__device__ float d_WhhD[4*DH*DH];     // decoder recurrent, interleaved, tf32-rounded
__device__ float d_WihS[4*DH*PTc];    // decoder stroke input, interleaved (fp32 exact)
__device__ float d_WihZ[4*DH*ZL];     // decoder z input, interleaved, tf32-rounded
__device__ float d_bDi[4*DH];         // decoder bias, interleaved
__device__ float d_Wvae[2*ZL*2*EH];   // [mu;sig] rows, tf32-rounded
__device__ float d_bvae[2*ZL];
__device__ float d_hE[2][Bv*EH];
__device__ float d_cE[Bv*EH];
__device__ float d_hback[Bv*EH];
__device__ float d_mups[Bv*2*ZL];
__device__ float d_z[Bv*ZL];
__device__ float d_hD[2][Bv*DH];
__device__ float d_cD[Bv*DH];
__device__ float d_zproj[Bv*4*DH];
__device__ float d_qpart[Tv*16];
__device__ unsigned g_count;
__device__ volatile unsigned g_gen;

// ---------------- helpers ----------------
__device__ __forceinline__ float sigf(float x) { return 1.f / (1.f + __expf(-x)); }
__device__ __forceinline__ float tanh_f(float x) {
    float ax = fabsf(x);
    float e = __expf(2.f * ax);
    float t = 1.f - 2.f / (e + 1.f);
    return copysignf(t, x);
}
__device__ __forceinline__ float wsum32(float v) {
    #pragma unroll
    for (int o = 16; o; o >>= 1) v += __shfl_xor_sync(0xffffffffu, v, o);
    return v;
}
__device__ __forceinline__ float wmax32(float v) {
    #pragma unroll
    for (int o = 16; o; o >>= 1) v = fmaxf(v, __shfl_xor_sync(0xffffffffu, v, o));
    return v;
}
__device__ __forceinline__ float f2tf(float x) {
    unsigned r; asm("cvt.rna.tf32.f32 %0, %1;" : "=r"(r) : "f"(x));
    return __uint_as_float(r);
}
__device__ __forceinline__ void mma8(float c[4], unsigned a0, unsigned a1, unsigned a2,
                                     unsigned a3, unsigned b0, unsigned b1) {
    asm volatile(
        "mma.sync.aligned.m16n8k8.row.col.f32.tf32.tf32.f32 "
        "{%0,%1,%2,%3}, {%4,%5,%6,%7}, {%8,%9}, {%0,%1,%2,%3};"
        : "+f"(c[0]), "+f"(c[1]), "+f"(c[2]), "+f"(c[3])
        : "r"(a0), "r"(a1), "r"(a2), "r"(a3), "r"(b0), "r"(b1));
}

__device__ __forceinline__ void grid_sync() {
    __threadfence();
    __syncthreads();
    if (threadIdx.x == 0) {
        unsigned gen = g_gen;
        if (atomicAdd(&g_count, 1u) == gridDim.x - 1) {
            g_count = 0;
            __threadfence();
            g_gen = gen + 1;
        } else {
            while (g_gen == gen) { __nanosleep(64); }
        }
    }
    __syncthreads();
    __threadfence();
}

// ---------------- tf32 MMA tile: C[MT*32 x 128] += A @ B^T ----------------
// 8 warps: wm in 0..1 (MT*16 rows each), wn in 0..3 (32 cols each).
// SMEM stride 36 words -> fragment LDS conflict-free. A may split at ksplit.
template<int MT>
__device__ __forceinline__ void mma_loop(
    const float* __restrict__ A, int lda,
    const float* __restrict__ A2, int lda2, int ksplit, int K,
    const float* __restrict__ B, int ldb, int brow0, int nvalid,
    int row0, float c[MT][4][4], float* As, float* Bs)
{
    const int tid = threadIdx.x;
    const int lane = tid & 31, warp = tid >> 5;
    const int wm = warp >> 2, wn = warp & 3;
    const int g = lane >> 2, tq = lane & 3;
    const int wrow = wm * (MT * 16);
    const int kk = (tid & 7) * 4;
    const int rr0 = tid >> 3;

    float4 pa[MT], pb[4];
    #pragma unroll
    for (int r = 0; r < MT; r++) {
        int row = row0 + rr0 + r * 32;
        const float* ap = (kk < ksplit) ? (A + (size_t)row * lda + kk)
                                        : (A2 + (size_t)row * lda2 + (kk - ksplit));
        pa[r] = *(const float4*)ap;
    }
    #pragma unroll
    for (int r = 0; r < 4; r++) {
        int col = rr0 + r * 32;
        pb[r] = (col < nvalid) ? *(const float4*)(B + (size_t)(brow0 + col) * ldb + kk)
                               : make_float4(0.f, 0.f, 0.f, 0.f);
    }

    for (int kb = 0; kb < K; kb += 32) {
        #pragma unroll
        for (int r = 0; r < MT; r++)
            *(float4*)(As + (rr0 + r * 32) * 36 + kk) = pa[r];
        #pragma unroll
        for (int r = 0; r < 4; r++)
            *(float4*)(Bs + (rr0 + r * 32) * 36 + kk) = pb[r];
        __syncthreads();
        if (kb + 32 < K) {
            int gk = kb + 32 + kk;
            #pragma unroll
            for (int r = 0; r < MT; r++) {
                int row = row0 + rr0 + r * 32;
                const float* ap = (gk < ksplit) ? (A + (size_t)row * lda + gk)
                                                : (A2 + (size_t)row * lda2 + (gk - ksplit));
                pa[r] = *(const float4*)ap;
            }
            #pragma unroll
            for (int r = 0; r < 4; r++) {
                int col = rr0 + r * 32;
                pb[r] = (col < nvalid) ? *(const float4*)(B + (size_t)(brow0 + col) * ldb + gk)
                                       : make_float4(0.f, 0.f, 0.f, 0.f);
            }
        }
        const unsigned* AsU = (const unsigned*)As;
        const unsigned* BsU = (const unsigned*)Bs;
        #pragma unroll
        for (int k8 = 0; k8 < 32; k8 += 8) {
            unsigned a[MT][4];
            #pragma unroll
            for (int mi = 0; mi < MT; mi++) {
                int rb = (wrow + mi * 16 + g) * 36 + k8 + tq;
                a[mi][0] = AsU[rb];
                a[mi][1] = AsU[rb + 8 * 36];
                a[mi][2] = AsU[rb + 4];
                a[mi][3] = AsU[rb + 8 * 36 + 4];
            }
            unsigned b[4][2];
            #pragma unroll
            for (int ni = 0; ni < 4; ni++) {
                int cb = (wn * 32 + ni * 8 + g) * 36 + k8 + tq;
                b[ni][0] = BsU[cb];
                b[ni][1] = BsU[cb + 4];
            }
            #pragma unroll
            for (int mi = 0; mi < MT; mi++)
                #pragma unroll
                for (int ni = 0; ni < 4; ni++)
                    mma8(c[mi][ni], a[mi][0], a[mi][1], a[mi][2], a[mi][3], b[ni][0], b[ni][1]);
        }
        __syncthreads();
    }
}

// ---------------- fused LSTM cell epilogue ----------------
// Interleaved cols: unit u = cols 4u..4u+3 (i,f,g,o). Lane pair (lane, lane^1)
// exchanges C-fragments so each lane owns a full (row, unit) gate quadruple.
template<int MT>
__device__ __forceinline__ void cell_epilogue(
    float c[MT][4][4], int row0, int col0, int H,
    const float* __restrict__ zproj, const float* __restrict__ bias,
    const float* __restrict__ Wih5,
    const float* __restrict__ s, int xt,
    float* __restrict__ cbuf, float* __restrict__ hnext)
{
    const int tid = threadIdx.x, lane = tid & 31, warp = tid >> 5;
    const int wm = warp >> 2, wn = warp & 3;
    const int g = lane >> 2, q = lane & 3;
    const bool hi = (q & 1) != 0;
    const int N4 = 4 * H;
    #pragma unroll
    for (int mi = 0; mi < MT; mi++) {
        int row = row0 + wm * (MT * 16) + mi * 16 + g + (hi ? 8 : 0);
        float xr[5];
        if (xt < 0) { xr[0] = 0.f; xr[1] = 0.f; xr[2] = 1.f; xr[3] = 0.f; xr[4] = 0.f; }
        else {
            const float* xp = s + ((size_t)row * Tv + xt) * PTc;
            #pragma unroll
            for (int k = 0; k < 5; k++) xr[k] = xp[k];
        }
        #pragma unroll
        for (int ni = 0; ni < 4; ni++) {
            float d0 = __shfl_xor_sync(0xffffffffu, c[mi][ni][0], 1);
            float d1 = __shfl_xor_sync(0xffffffffu, c[mi][ni][1], 1);
            float d2 = __shfl_xor_sync(0xffffffffu, c[mi][ni][2], 1);
            float d3 = __shfl_xor_sync(0xffffffffu, c[mi][ni][3], 1);
            float gi, gf, gg, go;
            if (!hi) { gi = c[mi][ni][0]; gf = c[mi][ni][1]; gg = d0; go = d1; }
            else     { gi = d2;           gf = d3;           gg = c[mi][ni][2]; go = c[mi][ni][3]; }
            int u4 = col0 + wn * 32 + ni * 8 + (q >> 1) * 4;
            float4 zb = zproj ? *(const float4*)(zproj + (size_t)row * N4 + u4)
                              : *(const float4*)(bias + u4);
            gi += zb.x; gf += zb.y; gg += zb.z; go += zb.w;
            const float* w5 = Wih5 + (size_t)u4 * 5;
            #pragma unroll
            for (int k = 0; k < 5; k++) {
                gi += xr[k] * w5[k];
                gf += xr[k] * w5[5 + k];
                gg += xr[k] * w5[10 + k];
                go += xr[k] * w5[15 + k];
            }
            size_t p = (size_t)row * H + (u4 >> 2);
            float cc = sigf(gf) * cbuf[p] + sigf(gi) * tanh_f(gg);
            cbuf[p] = cc;
            hnext[p] = sigf(go) * tanh_f(cc);
        }
    }
}

// ---------------- y epilogue: stage halves to SMEM, mixture transforms ----------------
__device__ __forceinline__ void y_epilogue(
    float c[4][4][4], int row0, int tstep,
    const float* __restrict__ bout, float* __restrict__ out,
    float* ys /* 64*128 */, float* wsum)
{
    const int tid = threadIdx.x, lane = tid & 31, warp = tid >> 5;
    const int wm = warp >> 2, wn = warp & 3;
    const int g = lane >> 2, q = lane & 3;
    for (int half = 0; half < 2; half++) {
        if (wm == half) {
            #pragma unroll
            for (int mi = 0; mi < 4; mi++)
                #pragma unroll
                for (int ni = 0; ni < 4; ni++)
                    #pragma unroll
                    for (int cid = 0; cid < 4; cid++) {
                        int col = wn * 32 + ni * 8 + 2 * q + (cid & 1);
                        if (col < OUTC) {
                            int r = mi * 16 + g + ((cid >= 2) ? 8 : 0);
                            ys[r * 128 + col] = c[mi][ni][cid] + bout[col];
                        }
                    }
        }
        __syncthreads();
        float qacc = 0.f;
        for (int rr = 0; rr < 8; rr++) {
            int r = warp * 8 + rr;
            int brow = row0 + half * 64 + r;
            float* orow = out + ((size_t)tstep * Bv + brow) * OUTC;
            float v = (lane < 20) ? ys[r * 128 + lane * 6] : -3.0e38f;
            float m = wmax32(v);
            float e = (lane < 20) ? __expf(v - m) : 0.f;
            float ss = wsum32(e);
            if (lane < 20) {
                orow[lane]       = e / ss;
                orow[20 + lane]  = ys[r * 128 + lane * 6 + 1];
                orow[40 + lane]  = ys[r * 128 + lane * 6 + 2];
                orow[60 + lane]  = __expf(ys[r * 128 + lane * 6 + 3]);
                orow[80 + lane]  = __expf(ys[r * 128 + lane * 6 + 4]);
                orow[100 + lane] = tanh_f(ys[r * 128 + lane * 6 + 5]);
            } else if (lane < 23) {
                float eq = __expf(ys[r * 128 + 120 + lane - 20]);
                orow[120 + lane - 20] = eq;   // normalized later by qknorm
                qacc += eq;
            }
        }
        float qs = wsum32(qacc);
        if (lane == 0) wsum[warp] = qs;
        __syncthreads();
        if (tid == 0) {
            float tot = 0.f;
            #pragma unroll
            for (int i = 0; i < 8; i++) tot += wsum[i];
            d_qpart[tstep * 16 + ((row0 + half * 64) >> 6)] = tot;
        }
        __syncthreads();
    }
}

__device__ __forceinline__ void qknorm(float* __restrict__ out, int t) {
    float tot = 0.f;
    #pragma unroll
    for (int i = 0; i < 16; i++) tot += d_qpart[t * 16 + i];
    float inv = 1.f / tot;
    for (int idx = blockIdx.x * NTHR + threadIdx.x; idx < Bv * 3; idx += gridDim.x * NTHR)
        out[((size_t)t * Bv + (idx / 3)) * OUTC + 120 + (idx % 3)] *= inv;
}

// ---------------- kernels ----------------
__global__ void reset_k() { g_count = 0; g_gen = 0; }

__global__ void prep_k(const float* __restrict__ eWihF, const float* __restrict__ eWhhF,
                       const float* __restrict__ ebF,  const float* __restrict__ eWihB,
                       const float* __restrict__ ebB,  const float* __restrict__ dWih,
                       const float* __restrict__ dWhh, const float* __restrict__ db,
                       const float* __restrict__ Wmu,  const float* __restrict__ bmu,
                       const float* __restrict__ Wsig, const float* __restrict__ bsig,
                       const float* __restrict__ s)
{
    int gt = blockIdx.x * blockDim.x + threadIdx.x;
    int gs = gridDim.x * blockDim.x;
    for (int i = gt; i < 4 * DH * DH; i += gs) {
        int n = i / DH, k = i - n * DH, j = n >> 2, g4 = n & 3;
        d_WhhD[i] = f2tf(dWhh[(size_t)(g4 * DH + j) * DH + k]);
    }
    for (int i = gt; i < 4 * DH * PTc; i += gs) {
        int n = i / PTc, k = i - n * PTc, j = n >> 2, g4 = n & 3;
        d_WihS[i] = dWih[(size_t)(g4 * DH + j) * (PTc + ZL) + k];
    }
    for (int i = gt; i < 4 * DH * ZL; i += gs) {
        int n = i / ZL, k = i - n * ZL, j = n >> 2, g4 = n & 3;
        d_WihZ[i] = f2tf(dWih[(size_t)(g4 * DH + j) * (PTc + ZL) + PTc + k]);
    }
    for (int i = gt; i < 4 * DH; i += gs) {
        int j = i >> 2, g4 = i & 3;
        d_bDi[i] = db[g4 * DH + j];
    }
    for (int i = gt; i < 4 * EH * EH; i += gs) {
        int n = i / EH, k = i - n * EH, j = n >> 2, g4 = n & 3;
        d_WhhF[i] = f2tf(eWhhF[(size_t)(g4 * EH + j) * EH + k]);
    }
    for (int i = gt; i < 4 * EH * PTc; i += gs) {
        int n = i / PTc, k = i - n * PTc, j = n >> 2, g4 = n & 3;
        d_WihF[i] = eWihF[(g4 * EH + j) * PTc + k];
    }
    for (int i = gt; i < 4 * EH; i += gs) {
        int j = i >> 2, g4 = i & 3;
        d_bF[i] = ebF[g4 * EH + j];
    }
    for (int i = gt; i < 2 * ZL * 2 * EH; i += gs) {
        int j = i / (2 * EH), k = i - j * (2 * EH);
        d_Wvae[i] = f2tf((j < ZL) ? Wmu[(size_t)j * (2 * EH) + k]
                                  : Wsig[(size_t)(j - ZL) * (2 * EH) + k]);
    }
    for (int i = gt; i < 2 * ZL; i += gs)
        d_bvae[i] = (i < ZL) ? bmu[i] : bsig[i - ZL];
    for (int i = gt; i < Bv * EH; i += gs) { d_hE[0][i] = 0.f; d_cE[i] = 0.f; }
    // backward encoder LSTM collapses to a single step (zero state, input x[T-1])
    for (int i = gt; i < Bv * EH; i += gs) {
        int b = i / EH, j = i - (i / EH) * EH;
        const float* xp = s + ((size_t)b * Tv + (Tv - 1)) * PTc;
        float gv[4];
        #pragma unroll
        for (int g = 0; g < 4; g++) {
            float a = ebB[g * EH + j];
            #pragma unroll
            for (int k = 0; k < 5; k++) a += eWihB[(size_t)(g * EH + j) * PTc + k] * xp[k];
            gv[g] = a;
        }
        float c = sigf(gv[0]) * tanh_f(gv[2]);
        d_hback[i] = sigf(gv[3]) * tanh_f(c);
    }
}

__global__ void __launch_bounds__(NTHR, 1) enc_kernel(const float* __restrict__ s) {
    __shared__ __align__(16) float sbuf[9216];
    float* As = sbuf; float* Bs = sbuf + 4608;
    int bid = blockIdx.x;                 // 128 blocks: 16 row-tiles(64) x 8 col-tiles(128)
    int row0 = (bid >> 3) * 64, col0 = (bid & 7) * 128;
    for (int t = 0; t < Tv; t++) {
        const float* hprev = d_hE[t & 1];
        float* hnext = d_hE[(t + 1) & 1];
        float c[2][4][4] = {};
        mma_loop<2>(hprev, EH, hprev, EH, EH, EH, d_WhhF, EH, col0, 128, row0, c, As, Bs);
        cell_epilogue<2>(c, row0, col0, EH, nullptr, d_bF, d_WihF, s, t, d_cE, hnext);
        grid_sync();
    }
}

__global__ void __launch_bounds__(NTHR, 1) vae1_mma() {
    __shared__ __align__(16) float sbuf[9216];
    float* As = sbuf; float* Bs = sbuf + 4608;
    int row0 = (blockIdx.x >> 1) * 128, col0 = (blockIdx.x & 1) * 128;
    float c[4][4][4] = {};
    mma_loop<4>(d_hE[0], EH, d_hback, EH, EH, 2 * EH, d_Wvae, 2 * EH, col0, 128, row0, c, As, Bs);
    const int lane = threadIdx.x & 31, warp = threadIdx.x >> 5;
    const int wm = warp >> 2, wn = warp & 3, g = lane >> 2, q = lane & 3;
    #pragma unroll
    for (int mi = 0; mi < 4; mi++)
        #pragma unroll
        for (int ni = 0; ni < 4; ni++)
            #pragma unroll
            for (int cid = 0; cid < 4; cid++) {
                int row = row0 + wm * 64 + mi * 16 + g + ((cid >= 2) ? 8 : 0);
                int col = col0 + wn * 32 + ni * 8 + 2 * q + (cid & 1);
                d_mups[(size_t)row * (2 * ZL) + col] = c[mi][ni][cid] + d_bvae[col];
            }
}

__global__ void zk(const float* __restrict__ eps) {
    int i = blockIdx.x * blockDim.x + threadIdx.x;
    if (i < Bv * ZL) {
        int b = i >> 7, j = i & 127;
        float mu = d_mups[(size_t)b * (2 * ZL) + j];
        float ps = d_mups[(size_t)b * (2 * ZL) + ZL + j];
        d_z[i] = mu + __expf(0.5f * ps) * eps[i];
    }
}

__global__ void __launch_bounds__(NTHR, 1) vae2_mma(const float* __restrict__ Wh0,
                                                    const float* __restrict__ bh0) {
    __shared__ __align__(16) float sbuf[9216];
    float* As = sbuf; float* Bs = sbuf + 4608;
    const int lane = threadIdx.x & 31, warp = threadIdx.x >> 5;
    const int wm = warp >> 2, wn = warp & 3, g = lane >> 2, q = lane & 3;
    float c[4][4][4] = {};
    if (blockIdx.x < 32) {     // h0 = tanh(z @ Wh0^T + bh0) : [1024 x 512]
        int row0 = (blockIdx.x >> 2) * 128, col0 = (blockIdx.x & 3) * 128;
        mma_loop<4>(d_z, ZL, d_z, ZL, ZL, ZL, Wh0, ZL, col0, 128, row0, c, As, Bs);
        #pragma unroll
        for (int mi = 0; mi < 4; mi++)
            #pragma unroll
            for (int ni = 0; ni < 4; ni++)
                #pragma unroll
                for (int cid = 0; cid < 4; cid++) {
                    int row = row0 + wm * 64 + mi * 16 + g + ((cid >= 2) ? 8 : 0);
                    int col = col0 + wn * 32 + ni * 8 + 2 * q + (cid & 1);
                    size_t p = (size_t)row * DH + col;
                    d_hD[0][p] = tanh_f(c[mi][ni][cid] + bh0[col]);
                    d_cD[p] = 0.f;
                }
    } else {                   // zproj = z @ WihZ^T + bDi : [1024 x 2048] interleaved
        int u = blockIdx.x - 32;
        int row0 = (u >> 4) * 128, col0 = (u & 15) * 128;
        mma_loop<4>(d_z, ZL, d_z, ZL, ZL, ZL, d_WihZ, ZL, col0, 128, row0, c, As, Bs);
        #pragma unroll
        for (int mi = 0; mi < 4; mi++)
            #pragma unroll
            for (int ni = 0; ni < 4; ni++)
                #pragma unroll
                for (int cid = 0; cid < 4; cid++) {
                    int row = row0 + wm * 64 + mi * 16 + g + ((cid >= 2) ? 8 : 0);
                    int col = col0 + wn * 32 + ni * 8 + 2 * q + (cid & 1);
                    d_zproj[(size_t)row * (4 * DH) + col] = c[mi][ni][cid] + d_bDi[col];
                }
    }
}

__global__ void __launch_bounds__(NTHR, 1) dec_kernel(const float* __restrict__ s,
    const float* __restrict__ Wout, const float* __restrict__ bout, float* __restrict__ out)
{
    __shared__ __align__(16) float sbuf[9216];
    __shared__ float wsum[8];
    float* As = sbuf; float* Bs = sbuf + 4608;
    int bid = blockIdx.x;   // 136 blocks: 128 gate tiles (8x16), 8 y tiles
    for (int t = 0; t < Tv; t++) {
        const float* hprev = d_hD[t & 1];
        float* hnext = d_hD[(t + 1) & 1];
        if (t >= 2) qknorm(out, t - 2);
        if (bid < 128) {
            int row0 = (bid >> 4) * 128, col0 = (bid & 15) * 128;
            float c[4][4][4] = {};
            mma_loop<4>(hprev, DH, hprev, DH, DH, DH, d_WhhD, DH, col0, 128, row0, c, As, Bs);
            cell_epilogue<4>(c, row0, col0, DH, d_zproj, nullptr, d_WihS, s, t - 1, d_cD, hnext);
        } else if (t >= 1) {
            int row0 = (bid - 128) * 128;
            float c[4][4][4] = {};
            mma_loop<4>(hprev, DH, hprev, DH, DH, DH, Wout, DH, 0, OUTC, row0, c, As, Bs);
            y_epilogue(c, row0, t - 1, bout, out, sbuf, wsum);
        }
        grid_sync();
    }
    qknorm(out, 254);
    if (bid < 8) {
        float c[4][4][4] = {};
        mma_loop<4>(d_hD[0], DH, d_hD[0], DH, DH, DH, Wout, DH, 0, OUTC, bid * 128, c, As, Bs);
        y_epilogue(c, bid * 128, 255, bout, out, sbuf, wsum);
    }
    grid_sync();
    qknorm(out, 255);
}

// ---------------- launch ----------------
extern "C" void kernel_launch(void* const* d_in, const int* in_sizes, int n_in,
                              void* d_out, int out_size)
{
    const float* s     = (const float*)d_in[0];
    const float* eps   = (const float*)d_in[1];
    const float* eWihF = (const float*)d_in[2];
    const float* eWhhF = (const float*)d_in[3];
    const float* ebF   = (const float*)d_in[4];
    const float* eWihB = (const float*)d_in[5];
    // d_in[6] = enc_Whh_b : unused (backward LSTM output only needs its first step)
    const float* ebB   = (const float*)d_in[7];
    const float* Wmu   = (const float*)d_in[8];
    const float* bmu   = (const float*)d_in[9];
    const float* Wsig  = (const float*)d_in[10];
    const float* bsig  = (const float*)d_in[11];
    const float* Wh0   = (const float*)d_in[12];
    const float* bh0   = (const float*)d_in[13];
    const float* dWih  = (const float*)d_in[14];
    const float* dWhh  = (const float*)d_in[15];
    const float* db    = (const float*)d_in[16];
    const float* Wout  = (const float*)d_in[17];
    const float* bout  = (const float*)d_in[18];
    float* out = (float*)d_out;

    reset_k<<<1, 1>>>();
    prep_k<<<2048, 256>>>(eWihF, eWhhF, ebF, eWihB, ebB, dWih, dWhh, db,
                          Wmu, bmu, Wsig, bsig, s);
    enc_kernel<<<128, NTHR>>>(s);
    vae1_mma<<<16, NTHR>>>();
    zk<<<(Bv * ZL + 255) / 256, 256>>>(eps);
    vae2_mma<<<160, NTHR>>>(Wh0, bh0);
    dec_kernel<<<136, NTHR>>>(s, Wout, bout, out);
}

// round 7
// speedup vs baseline: 1.0453x; 1.0453x over previous
#include <cuda_runtime.h>
#include <math.h>
#include <stdint.h>
#include <stddef.h>

#define Bv 1024
#define Tv 256
#define EH 256
#define DH 512
#define ZL 128
#define PTc 5
#define OUTC 123

// ---------------- device scratch ----------------
__device__ float d_WhhF[4*EH*EH];     // encoder recurrent, gate-interleaved, tf32-rounded
__device__ float d_WihF[4*EH*PTc];
__device__ float d_bF[4*EH];
__device__ float d_WhhD[4*DH*DH];     // decoder recurrent, interleaved, tf32-rounded
__device__ float d_WihS[4*DH*PTc];
__device__ float d_bDi[4*DH];
__device__ float d_WvaeT[512*256];    // [k][j], j<128: mu row j, else sig row j-128
__device__ float d_bvae[2*ZL];
__device__ float d_Wh0T[128*512];     // [k][n]
__device__ float d_WzT[128*2048];     // [k][n-interleaved]
__device__ float d_hE[2][Bv*EH];
__device__ float d_hback[Bv*EH];
__device__ float d_mups[Bv*2*ZL];
__device__ float d_z[Bv*ZL];
__device__ float d_hD[2][Bv*DH];
__device__ float d_zproj[Bv*4*DH];
__device__ float d_qpart[Tv*16];
__device__ volatile unsigned g_flagsE[128];
__device__ volatile unsigned g_flagsD[136];

// ---------------- scalar helpers ----------------
__device__ __forceinline__ float sigf(float x) { return 1.f / (1.f + __expf(-x)); }
__device__ __forceinline__ float tanh_f(float x) {
    float ax = fabsf(x);
    float e = __expf(2.f * ax);
    float t = 1.f - 2.f / (e + 1.f);
    return copysignf(t, x);
}
__device__ __forceinline__ float wsum32(float v) {
    #pragma unroll
    for (int o = 16; o; o >>= 1) v += __shfl_xor_sync(0xffffffffu, v, o);
    return v;
}
__device__ __forceinline__ float wmax32(float v) {
    #pragma unroll
    for (int o = 16; o; o >>= 1) v = fmaxf(v, __shfl_xor_sync(0xffffffffu, v, o));
    return v;
}
__device__ __forceinline__ float f2tf(float x) {
    unsigned r; asm("cvt.rna.tf32.f32 %0, %1;" : "=r"(r) : "f"(x));
    return __uint_as_float(r);
}
__device__ __forceinline__ void mma8(float c[4], unsigned a0, unsigned a1, unsigned a2,
                                     unsigned a3, unsigned b0, unsigned b1) {
    asm volatile(
        "mma.sync.aligned.m16n8k8.row.col.f32.tf32.tf32.f32 "
        "{%0,%1,%2,%3}, {%4,%5,%6,%7}, {%8,%9}, {%0,%1,%2,%3};"
        : "+f"(c[0]), "+f"(c[1]), "+f"(c[2]), "+f"(c[3])
        : "r"(a0), "r"(a1), "r"(a2), "r"(a3), "r"(b0), "r"(b1));
}

// flag-array grid barrier: per-block release store + 32-lane poll (no atomic serialization)
__device__ __forceinline__ void gsync(volatile unsigned* flags, int nblk, unsigned gen) {
    __threadfence();
    __syncthreads();
    if (threadIdx.x == 0) flags[blockIdx.x] = gen;
    if (threadIdx.x < 32) {
        for (int i = threadIdx.x; i < nblk; i += 32)
            while (flags[i] < gen) { }
    }
    __threadfence();
    __syncthreads();
}

// ---------------- cp.async ----------------
__device__ __forceinline__ uint32_t s2u(const void* p) { return (uint32_t)__cvta_generic_to_shared(p); }
__device__ __forceinline__ void cp16(uint32_t d, const void* s) {
    asm volatile("cp.async.cg.shared.global [%0], [%1], 16;" :: "r"(d), "l"(s));
}
__device__ __forceinline__ void cp16p(uint32_t d, const void* s, bool v) {
    int sz = v ? 16 : 0;
    asm volatile("cp.async.cg.shared.global [%0], [%1], 16, %2;" :: "r"(d), "l"(s), "r"(sz));
}
__device__ __forceinline__ void cp_commit() { asm volatile("cp.async.commit_group;" ::: "memory"); }
template<int N> __device__ __forceinline__ void cp_wait() {
    asm volatile("cp.async.wait_group %0;" :: "n"(N) : "memory");
}

// issue one 32-K chunk's loads into a stage (A rows = MT*32, B rows = 128; stride 36 floats)
template<int MT>
__device__ __forceinline__ void issue_chunk(
    const float* __restrict__ A, int lda,
    const float* __restrict__ B, int ldb, int nvalid,
    float* sA, int kb)
{
    const int tid = threadIdx.x;
    float* sB = sA + MT * 32 * 36;
    #pragma unroll
    for (int it = 0; it < MT; it++) {
        int tq = tid + it * 256, row = tq >> 3, seg = tq & 7;
        cp16(s2u(sA + row * 36 + seg * 4), A + (size_t)row * lda + kb + seg * 4);
    }
    #pragma unroll
    for (int it = 0; it < 4; it++) {
        int tq = tid + it * 256, row = tq >> 3, seg = tq & 7;
        bool v = row < nvalid;
        cp16p(s2u(sB + row * 36 + seg * 4), B + (size_t)(v ? row : 0) * ldb + kb + seg * 4, v);
    }
}

// C[MT*32 x 128] += A[MT*32 x K] @ B[128 x K]^T, 4-stage cp.async pipeline.
template<int MT>
__device__ __forceinline__ void mma_pipe(
    const float* __restrict__ A, int lda, int K,
    const float* __restrict__ B, int ldb, int nvalid,
    float* stg, float c[MT][4][4])
{
    const int STAGE = MT * 32 * 36 + 128 * 36;
    const int tid = threadIdx.x, lane = tid & 31, warp = tid >> 5;
    const int wm = warp >> 2, wn = warp & 3, g = lane >> 2, tq = lane & 3;
    const int wrow = wm * (MT * 16);
    const int nch = K / 32;

    issue_chunk<MT>(A, lda, B, ldb, nvalid, stg, 0); cp_commit();
    if (nch > 1) issue_chunk<MT>(A, lda, B, ldb, nvalid, stg + STAGE, 32);
    cp_commit();
    if (nch > 2) issue_chunk<MT>(A, lda, B, ldb, nvalid, stg + 2 * STAGE, 64);
    cp_commit();

    for (int i = 0; i < nch; i++) {
        if (i + 3 < nch)
            issue_chunk<MT>(A, lda, B, ldb, nvalid, stg + ((i + 3) & 3) * STAGE, (i + 3) * 32);
        cp_commit();
        cp_wait<3>();
        __syncthreads();
        const unsigned* AsU = (const unsigned*)(stg + (i & 3) * STAGE);
        const unsigned* BsU = AsU + MT * 32 * 36;
        #pragma unroll
        for (int k8 = 0; k8 < 32; k8 += 8) {
            unsigned a[MT][4];
            #pragma unroll
            for (int mi = 0; mi < MT; mi++) {
                int rb = (wrow + mi * 16 + g) * 36 + k8 + tq;
                a[mi][0] = AsU[rb];
                a[mi][1] = AsU[rb + 8 * 36];
                a[mi][2] = AsU[rb + 4];
                a[mi][3] = AsU[rb + 8 * 36 + 4];
            }
            unsigned b[4][2];
            #pragma unroll
            for (int ni = 0; ni < 4; ni++) {
                int cb = (wn * 32 + ni * 8 + g) * 36 + k8 + tq;
                b[ni][0] = BsU[cb];
                b[ni][1] = BsU[cb + 4];
            }
            #pragma unroll
            for (int mi = 0; mi < MT; mi++)
                #pragma unroll
                for (int ni = 0; ni < 4; ni++)
                    mma8(c[mi][ni], a[mi][0], a[mi][1], a[mi][2], a[mi][3], b[ni][0], b[ni][1]);
        }
        __syncthreads();
    }
}

// ---------------- fused LSTM cell epilogue (c-state in registers) ----------------
template<int MT>
__device__ __forceinline__ void cell_epi(
    float c[MT][4][4], int row0, int col0, int H,
    const float* zS, const float* bS, const float* w5S,
    const float* __restrict__ sPtr, int xt,
    float* __restrict__ hnext, float* cst)
{
    const int tid = threadIdx.x, lane = tid & 31, warp = tid >> 5;
    const int wm = warp >> 2, wn = warp & 3, g = lane >> 2, q = lane & 3;
    const bool hi = (q & 1) != 0;
    #pragma unroll
    for (int mi = 0; mi < MT; mi++) {
        int rowt = wm * (MT * 16) + mi * 16 + g + (hi ? 8 : 0);
        int row = row0 + rowt;
        float xr[5];
        if (xt < 0) { xr[0] = 0.f; xr[1] = 0.f; xr[2] = 1.f; xr[3] = 0.f; xr[4] = 0.f; }
        else {
            const float* xp = sPtr + ((size_t)row * Tv + xt) * PTc;
            #pragma unroll
            for (int k = 0; k < 5; k++) xr[k] = xp[k];
        }
        #pragma unroll
        for (int ni = 0; ni < 4; ni++) {
            float d0 = __shfl_xor_sync(0xffffffffu, c[mi][ni][0], 1);
            float d1 = __shfl_xor_sync(0xffffffffu, c[mi][ni][1], 1);
            float d2 = __shfl_xor_sync(0xffffffffu, c[mi][ni][2], 1);
            float d3 = __shfl_xor_sync(0xffffffffu, c[mi][ni][3], 1);
            float gi, gf, gg, go;
            if (!hi) { gi = c[mi][ni][0]; gf = c[mi][ni][1]; gg = d0; go = d1; }
            else     { gi = d2;           gf = d3;           gg = c[mi][ni][2]; go = c[mi][ni][3]; }
            int lc = wn * 32 + ni * 8 + (q >> 1) * 4;
            if (zS) {
                const float* zp = zS + rowt * 129 + lc;
                gi += zp[0]; gf += zp[1]; gg += zp[2]; go += zp[3];
            } else {
                gi += bS[lc]; gf += bS[lc + 1]; gg += bS[lc + 2]; go += bS[lc + 3];
            }
            const float* w5 = w5S + lc * 5;
            #pragma unroll
            for (int k = 0; k < 5; k++) {
                gi += xr[k] * w5[k];
                gf += xr[k] * w5[5 + k];
                gg += xr[k] * w5[10 + k];
                go += xr[k] * w5[15 + k];
            }
            float cc = sigf(gf) * cst[mi * 4 + ni] + sigf(gi) * tanh_f(gg);
            cst[mi * 4 + ni] = cc;
            hnext[(size_t)row * H + ((col0 + lc) >> 2)] = sigf(go) * tanh_f(cc);
        }
    }
}

// ---------------- y epilogue ----------------
__device__ __forceinline__ void y_epi(
    float c[4][4][4], int row0, int tstep,
    const float* __restrict__ bout, float* __restrict__ out,
    float* ys /*64*128*/, float* wsum)
{
    const int tid = threadIdx.x, lane = tid & 31, warp = tid >> 5;
    const int wm = warp >> 2, wn = warp & 3, g = lane >> 2, q = lane & 3;
    for (int half = 0; half < 2; half++) {
        if (wm == half) {
            #pragma unroll
            for (int mi = 0; mi < 4; mi++)
                #pragma unroll
                for (int ni = 0; ni < 4; ni++)
                    #pragma unroll
                    for (int cid = 0; cid < 4; cid++) {
                        int col = wn * 32 + ni * 8 + 2 * q + (cid & 1);
                        if (col < OUTC) {
                            int r = mi * 16 + g + ((cid >= 2) ? 8 : 0);
                            ys[r * 128 + col] = c[mi][ni][cid] + bout[col];
                        }
                    }
        }
        __syncthreads();
        float qacc = 0.f;
        for (int rr = 0; rr < 8; rr++) {
            int r = warp * 8 + rr;
            int brow = row0 + half * 64 + r;
            float* orow = out + ((size_t)tstep * Bv + brow) * OUTC;
            float v = (lane < 20) ? ys[r * 128 + lane * 6] : -3.0e38f;
            float m = wmax32(v);
            float e = (lane < 20) ? __expf(v - m) : 0.f;
            float ss = wsum32(e);
            if (lane < 20) {
                orow[lane]       = e / ss;
                orow[20 + lane]  = ys[r * 128 + lane * 6 + 1];
                orow[40 + lane]  = ys[r * 128 + lane * 6 + 2];
                orow[60 + lane]  = __expf(ys[r * 128 + lane * 6 + 3]);
                orow[80 + lane]  = __expf(ys[r * 128 + lane * 6 + 4]);
                orow[100 + lane] = tanh_f(ys[r * 128 + lane * 6 + 5]);
            } else if (lane < 23) {
                float eq = __expf(ys[r * 128 + 120 + lane - 20]);
                orow[120 + lane - 20] = eq;   // normalized later by qknorm
                qacc += eq;
            }
        }
        float qs = wsum32(qacc);
        if (lane == 0) wsum[warp] = qs;
        __syncthreads();
        if (tid == 0) {
            float tot = 0.f;
            #pragma unroll
            for (int i = 0; i < 8; i++) tot += wsum[i];
            d_qpart[tstep * 16 + ((row0 + half * 64) >> 6)] = tot;
        }
        __syncthreads();
    }
}

__device__ __forceinline__ void qknorm(float* __restrict__ out, int t) {
    float tot = 0.f;
    #pragma unroll
    for (int i = 0; i < 16; i++) tot += d_qpart[t * 16 + i];
    float inv = 1.f / tot;
    for (int idx = blockIdx.x * blockDim.x + threadIdx.x; idx < Bv * 3; idx += gridDim.x * blockDim.x)
        out[((size_t)t * Bv + (idx / 3)) * OUTC + 120 + (idx % 3)] *= inv;
}

// ---------------- kernels ----------------
__global__ void reset_k() {
    int i = threadIdx.x;
    if (i < 128) g_flagsE[i] = 0;
    if (i < 136) g_flagsD[i] = 0;
}

__global__ void prep_k(const float* __restrict__ eWihF, const float* __restrict__ eWhhF,
                       const float* __restrict__ ebF,  const float* __restrict__ eWihB,
                       const float* __restrict__ ebB,  const float* __restrict__ dWih,
                       const float* __restrict__ dWhh, const float* __restrict__ db,
                       const float* __restrict__ Wmu,  const float* __restrict__ bmu,
                       const float* __restrict__ Wsig, const float* __restrict__ bsig,
                       const float* __restrict__ Wh0,  const float* __restrict__ s)
{
    int gt = blockIdx.x * blockDim.x + threadIdx.x;
    int gs = gridDim.x * blockDim.x;
    for (int i = gt; i < 4 * DH * DH; i += gs) {
        int n = i / DH, k = i - n * DH, j = n >> 2, g4 = n & 3;
        d_WhhD[i] = f2tf(dWhh[(size_t)(g4 * DH + j) * DH + k]);
    }
    for (int i = gt; i < 4 * DH * PTc; i += gs) {
        int n = i / PTc, k = i - n * PTc, j = n >> 2, g4 = n & 3;
        d_WihS[i] = dWih[(size_t)(g4 * DH + j) * (PTc + ZL) + k];
    }
    for (int i = gt; i < ZL * 4 * DH; i += gs) {
        int k = i / (4 * DH), n = i - k * (4 * DH), j = n >> 2, g4 = n & 3;
        d_WzT[i] = dWih[(size_t)(g4 * DH + j) * (PTc + ZL) + PTc + k];
    }
    for (int i = gt; i < 4 * DH; i += gs) {
        int j = i >> 2, g4 = i & 3;
        d_bDi[i] = db[g4 * DH + j];
    }
    for (int i = gt; i < 4 * EH * EH; i += gs) {
        int n = i / EH, k = i - n * EH, j = n >> 2, g4 = n & 3;
        d_WhhF[i] = f2tf(eWhhF[(size_t)(g4 * EH + j) * EH + k]);
    }
    for (int i = gt; i < 4 * EH * PTc; i += gs) {
        int n = i / PTc, k = i - n * PTc, j = n >> 2, g4 = n & 3;
        d_WihF[i] = eWihF[(g4 * EH + j) * PTc + k];
    }
    for (int i = gt; i < 4 * EH; i += gs) {
        int j = i >> 2, g4 = i & 3;
        d_bF[i] = ebF[g4 * EH + j];
    }
    for (int i = gt; i < 512 * 256; i += gs) {
        int k = i >> 8, j = i & 255;
        d_WvaeT[i] = (j < ZL) ? Wmu[(size_t)j * 512 + k] : Wsig[(size_t)(j - ZL) * 512 + k];
    }
    for (int i = gt; i < 2 * ZL; i += gs) d_bvae[i] = (i < ZL) ? bmu[i] : bsig[i - ZL];
    for (int i = gt; i < ZL * DH; i += gs) {
        int k = i / DH, n = i - k * DH;
        d_Wh0T[i] = Wh0[(size_t)n * ZL + k];
    }
    for (int i = gt; i < Bv * EH; i += gs) d_hE[0][i] = 0.f;
    for (int i = gt; i < Bv * EH; i += gs) {   // backward enc LSTM = 1 step
        int b = i / EH, j = i - (i / EH) * EH;
        const float* xp = s + ((size_t)b * Tv + (Tv - 1)) * PTc;
        float gv[4];
        #pragma unroll
        for (int g = 0; g < 4; g++) {
            float a = ebB[g * EH + j];
            #pragma unroll
            for (int k = 0; k < 5; k++) a += eWihB[(size_t)(g * EH + j) * PTc + k] * xp[k];
            gv[g] = a;
        }
        float c = sigf(gv[0]) * tanh_f(gv[2]);
        d_hback[i] = sigf(gv[3]) * tanh_f(c);
    }
}

// encoder: 128 blocks = 16 row-tiles(64) x 8 col-tiles(128), K=256
#define ENC_STG (64*36 + 128*36)
#define ENC_SMF (4*ENC_STG + 640 + 128)
__global__ void __launch_bounds__(256, 1) enc_kernel(const float* __restrict__ s) {
    extern __shared__ __align__(16) float dsm[];
    const int tid = threadIdx.x, bid = blockIdx.x;
    int row0 = (bid >> 3) * 64, col0 = (bid & 7) * 128;
    float* stg = dsm;
    float* w5S = dsm + 4 * ENC_STG;
    float* bS  = w5S + 640;
    for (int i = tid; i < 128 * 5; i += 256) w5S[i] = d_WihF[(size_t)col0 * 5 + i];
    for (int i = tid; i < 128; i += 256) bS[i] = d_bF[col0 + i];
    __syncthreads();
    float cst[8];
    #pragma unroll
    for (int i = 0; i < 8; i++) cst[i] = 0.f;
    for (int t = 0; t < Tv; t++) {
        const float* hprev = d_hE[t & 1];
        float* hnext = d_hE[(t + 1) & 1];
        float c[2][4][4] = {};
        mma_pipe<2>(hprev + (size_t)row0 * EH, EH, EH,
                    d_WhhF + (size_t)col0 * EH, EH, 128, stg, c);
        cell_epi<2>(c, row0, col0, EH, nullptr, bS, w5S, s, t, hnext, cst);
        gsync(g_flagsE, 128, t + 1);
    }
}

__global__ void vae1_k() {   // 256 blocks x 256 thr, 4 rows each
    __shared__ float h[4][512];
    int b0 = blockIdx.x * 4, tid = threadIdx.x;
    for (int i = tid; i < 4 * 512; i += 256) {
        int r = i >> 9, k = i & 511;
        h[r][k] = (k < 256) ? d_hE[0][(size_t)(b0 + r) * 256 + k]
                            : d_hback[(size_t)(b0 + r) * 256 + k - 256];
    }
    __syncthreads();
    float acc[4];
    #pragma unroll
    for (int r = 0; r < 4; r++) acc[r] = d_bvae[tid];
    for (int k = 0; k < 512; k++) {
        float w = d_WvaeT[k * 256 + tid];
        #pragma unroll
        for (int r = 0; r < 4; r++) acc[r] += h[r][k] * w;
    }
    #pragma unroll
    for (int r = 0; r < 4; r++) d_mups[(size_t)(b0 + r) * 256 + tid] = acc[r];
}

__global__ void zk(const float* __restrict__ eps) {
    int i = blockIdx.x * blockDim.x + threadIdx.x;
    if (i < Bv * ZL) {
        int b = i >> 7, j = i & 127;
        d_z[i] = d_mups[(size_t)b * 256 + j]
               + __expf(0.5f * d_mups[(size_t)b * 256 + 128 + j]) * eps[i];
    }
}

__global__ void vae2a_k(const float* __restrict__ bh0) {   // 256 blocks x 512 thr
    __shared__ float z4[4][128];
    int b0 = blockIdx.x * 4, tid = threadIdx.x;
    for (int i = tid; i < 4 * 128; i += 512) z4[i >> 7][i & 127] = d_z[(size_t)b0 * 128 + i];
    __syncthreads();
    float acc[4];
    #pragma unroll
    for (int r = 0; r < 4; r++) acc[r] = bh0[tid];
    for (int k = 0; k < 128; k++) {
        float w = d_Wh0T[k * 512 + tid];
        #pragma unroll
        for (int r = 0; r < 4; r++) acc[r] += z4[r][k] * w;
    }
    #pragma unroll
    for (int r = 0; r < 4; r++) d_hD[0][(size_t)(b0 + r) * 512 + tid] = tanh_f(acc[r]);
}

__global__ void vae2b_k() {   // 512 blocks x 256 thr
    __shared__ float z2[2][128];
    int b0 = blockIdx.x * 2, tid = threadIdx.x;
    for (int i = tid; i < 2 * 128; i += 256) z2[i >> 7][i & 127] = d_z[(size_t)b0 * 128 + i];
    __syncthreads();
    float acc[16];
    #pragma unroll
    for (int i = 0; i < 16; i++) acc[i] = 0.f;
    for (int k = 0; k < 128; k++) {
        float z0 = z2[0][k], z1 = z2[1][k];
        #pragma unroll
        for (int m = 0; m < 8; m++) {
            float w = d_WzT[(size_t)k * 2048 + tid + 256 * m];
            acc[m] += z0 * w;
            acc[8 + m] += z1 * w;
        }
    }
    #pragma unroll
    for (int m = 0; m < 8; m++) {
        float bb = d_bDi[tid + 256 * m];
        d_zproj[(size_t)b0 * 2048 + tid + 256 * m] = acc[m] + bb;
        d_zproj[(size_t)(b0 + 1) * 2048 + tid + 256 * m] = acc[8 + m] + bb;
    }
}

// decoder: 136 blocks = 128 gate tiles (8 row x 16 col) + 8 y tiles, K=512
#define DEC_STG (128*36 + 128*36)
#define DEC_SMF (4*DEC_STG + 128*129 + 640 + 8)
__global__ void __launch_bounds__(256, 1) dec_kernel(const float* __restrict__ s,
    const float* __restrict__ Wout, const float* __restrict__ bout, float* __restrict__ out)
{
    extern __shared__ __align__(16) float dsm[];
    const int tid = threadIdx.x, bid = blockIdx.x;
    float* stg = dsm;
    float* zS  = dsm + 4 * DEC_STG;
    float* w5S = zS + 128 * 129;
    float* wsum = w5S + 640;
    float* ys  = dsm;   // overlays staging (used only by y blocks after MMA drains)
    float cst[16];
    #pragma unroll
    for (int i = 0; i < 16; i++) cst[i] = 0.f;
    int row0, col0 = 0;
    if (bid < 128) {
        row0 = (bid >> 4) * 128; col0 = (bid & 15) * 128;
        for (int i = tid; i < 128 * 128; i += 256) {
            int r = i >> 7, c = i & 127;
            zS[r * 129 + c] = d_zproj[(size_t)(row0 + r) * 2048 + col0 + c];
        }
        for (int i = tid; i < 128 * 5; i += 256) w5S[i] = d_WihS[(size_t)col0 * 5 + i];
        __syncthreads();
    } else {
        row0 = (bid - 128) * 128;
    }
    for (int t = 0; t < Tv; t++) {
        const float* hprev = d_hD[t & 1];
        if (t >= 2) qknorm(out, t - 2);
        if (bid < 128) {
            float* hnext = d_hD[(t + 1) & 1];
            float c[4][4][4] = {};
            mma_pipe<4>(hprev + (size_t)row0 * DH, DH, DH,
                        d_WhhD + (size_t)col0 * DH, DH, 128, stg, c);
            cell_epi<4>(c, row0, col0, DH, zS, nullptr, w5S, s, t - 1, hnext, cst);
        } else if (t >= 1) {
            float c[4][4][4] = {};
            mma_pipe<4>(hprev + (size_t)row0 * DH, DH, DH, Wout, DH, OUTC, stg, c);
            y_epi(c, row0, t - 1, bout, out, ys, wsum);
        }
        gsync(g_flagsD, 136, t + 1);
    }
    qknorm(out, 254);
    if (bid >= 128) {
        float c[4][4][4] = {};
        mma_pipe<4>(d_hD[0] + (size_t)row0 * DH, DH, DH, Wout, DH, OUTC, stg, c);
        y_epi(c, row0, 255, bout, out, ys, wsum);
    }
    gsync(g_flagsD, 136, Tv + 1);
    qknorm(out, 255);
}

// ---------------- launch ----------------
extern "C" void kernel_launch(void* const* d_in, const int* in_sizes, int n_in,
                              void* d_out, int out_size)
{
    const float* s     = (const float*)d_in[0];
    const float* eps   = (const float*)d_in[1];
    const float* eWihF = (const float*)d_in[2];
    const float* eWhhF = (const float*)d_in[3];
    const float* ebF   = (const float*)d_in[4];
    const float* eWihB = (const float*)d_in[5];
    // d_in[6] = enc_Whh_b : unused (backward LSTM output only needs its first step)
    const float* ebB   = (const float*)d_in[7];
    const float* Wmu   = (const float*)d_in[8];
    const float* bmu   = (const float*)d_in[9];
    const float* Wsig  = (const float*)d_in[10];
    const float* bsig  = (const float*)d_in[11];
    const float* Wh0   = (const float*)d_in[12];
    const float* bh0   = (const float*)d_in[13];
    const float* dWih  = (const float*)d_in[14];
    const float* dWhh  = (const float*)d_in[15];
    const float* db    = (const float*)d_in[16];
    const float* Wout  = (const float*)d_in[17];
    const float* bout  = (const float*)d_in[18];
    float* out = (float*)d_out;

    static int inited = 0;
    if (!inited) {
        cudaFuncSetAttribute(enc_kernel, cudaFuncAttributeMaxDynamicSharedMemorySize, ENC_SMF * 4);
        cudaFuncSetAttribute(dec_kernel, cudaFuncAttributeMaxDynamicSharedMemorySize, DEC_SMF * 4);
        inited = 1;
    }

    reset_k<<<1, 256>>>();
    prep_k<<<2048, 256>>>(eWihF, eWhhF, ebF, eWihB, ebB, dWih, dWhh, db,
                          Wmu, bmu, Wsig, bsig, Wh0, s);
    enc_kernel<<<128, 256, ENC_SMF * 4>>>(s);
    vae1_k<<<256, 256>>>();
    zk<<<(Bv * ZL + 255) / 256, 256>>>(eps);
    vae2a_k<<<256, 512>>>(bh0);
    vae2b_k<<<512, 256>>>();
    dec_kernel<<<136, 256, DEC_SMF * 4>>>(s, Wout, bout, out);
}

// round 8
// speedup vs baseline: 1.4479x; 1.3852x over previous
#include <cuda_runtime.h>
#include <cuda_fp16.h>
#include <math.h>
#include <stdint.h>
#include <stddef.h>

#define Bv 1024
#define Tv 256
#define EH 256
#define DH 512
#define ZL 128
#define PTc 5
#define OUTC 123

// ---------------- device scratch ----------------
__device__ __half d_WhhFh[4*EH*EH];   // encoder recurrent, gate-interleaved, fp16
__device__ float  d_WihF[4*EH*PTc];
__device__ float  d_bF[4*EH];
__device__ __half d_WhhDh[4*DH*DH];   // decoder recurrent, interleaved, fp16
__device__ float  d_WihS[4*DH*PTc];
__device__ float  d_bDi[4*DH];
__device__ __half d_Wouth[128*DH];    // [n][k], rows >= OUTC zeroed
__device__ float  d_WvaeT[512*256];   // [k][j], j<128: mu, else sig
__device__ float  d_bvae[2*ZL];
__device__ float  d_Wh0T[128*512];    // [k][n]
__device__ float  d_WzT[128*2048];    // [k][n-interleaved]
__device__ __half d_hEh[2][Bv*EH];
__device__ float  d_hback[Bv*EH];
__device__ float  d_mups[Bv*2*ZL];
__device__ float  d_z[Bv*ZL];
__device__ __half d_hDh[2][Bv*DH];
__device__ float  d_zproj[Bv*4*DH];
__device__ float  d_qpart[Tv*16];
__device__ volatile unsigned g_flagsE[128];
__device__ volatile unsigned g_flagsD[136];

// ---------------- scalar helpers ----------------
__device__ __forceinline__ float sigf(float x) { return 1.f / (1.f + __expf(-x)); }
__device__ __forceinline__ float tanh_f(float x) {
    float ax = fabsf(x);
    float e = __expf(2.f * ax);
    float t = 1.f - 2.f / (e + 1.f);
    return copysignf(t, x);
}
__device__ __forceinline__ float wsum32(float v) {
    #pragma unroll
    for (int o = 16; o; o >>= 1) v += __shfl_xor_sync(0xffffffffu, v, o);
    return v;
}
__device__ __forceinline__ float wmax32(float v) {
    #pragma unroll
    for (int o = 16; o; o >>= 1) v = fmaxf(v, __shfl_xor_sync(0xffffffffu, v, o));
    return v;
}
__device__ __forceinline__ void mma16(float c[4], unsigned a0, unsigned a1, unsigned a2,
                                      unsigned a3, unsigned b0, unsigned b1) {
    asm volatile(
        "mma.sync.aligned.m16n8k16.row.col.f32.f16.f16.f32 "
        "{%0,%1,%2,%3}, {%4,%5,%6,%7}, {%8,%9}, {%0,%1,%2,%3};"
        : "+f"(c[0]), "+f"(c[1]), "+f"(c[2]), "+f"(c[3])
        : "r"(a0), "r"(a1), "r"(a2), "r"(a3), "r"(b0), "r"(b1));
}

// flag-array grid barrier
__device__ __forceinline__ void gsync(volatile unsigned* flags, int nblk, unsigned gen) {
    __threadfence();
    __syncthreads();
    if (threadIdx.x == 0) flags[blockIdx.x] = gen;
    if (threadIdx.x < 32) {
        for (int i = threadIdx.x; i < nblk; i += 32)
            while (flags[i] < gen) { }
    }
    __threadfence();
    __syncthreads();
}

// ---------------- cp.async ----------------
__device__ __forceinline__ uint32_t s2u(const void* p) { return (uint32_t)__cvta_generic_to_shared(p); }
__device__ __forceinline__ void cp16(uint32_t d, const void* s) {
    asm volatile("cp.async.cg.shared.global [%0], [%1], 16;" :: "r"(d), "l"(s));
}
__device__ __forceinline__ void cp_commit() { asm volatile("cp.async.commit_group;" ::: "memory"); }
template<int N> __device__ __forceinline__ void cp_wait() {
    asm volatile("cp.async.wait_group %0;" :: "n"(N) : "memory");
}

// one 32-K chunk of halves into a stage; row stride 40 halves (conflict-free fragments)
template<int MT>
__device__ __forceinline__ void issue_chunk(
    const __half* __restrict__ A, int lda,
    const __half* __restrict__ B, int ldb,
    __half* sA, int kb)
{
    const int tid = threadIdx.x;
    __half* sB = sA + MT * 32 * 40;
    #pragma unroll
    for (int it = 0; it < MT / 2; it++) {
        int tq = tid + it * 256, row = tq >> 2, seg = tq & 3;
        cp16(s2u(sA + row * 40 + seg * 8), A + (size_t)row * lda + kb + seg * 8);
    }
    #pragma unroll
    for (int it = 0; it < 2; it++) {
        int tq = tid + it * 256, row = tq >> 2, seg = tq & 3;
        cp16(s2u(sB + row * 40 + seg * 8), B + (size_t)row * ldb + kb + seg * 8);
    }
}

// C[MT*32 x 128] += A[MT*32 x K] @ B[128 x K]^T, fp16 mma, 4-stage cp.async pipeline.
template<int MT>
__device__ __forceinline__ void mma_pipe(
    const __half* __restrict__ A, int lda, int K,
    const __half* __restrict__ B, int ldb,
    __half* stg, float c[MT][4][4])
{
    const int STAGE = (MT * 32 + 128) * 40;   // halves
    const int tid = threadIdx.x, lane = tid & 31, warp = tid >> 5;
    const int wm = warp >> 2, wn = warp & 3, g = lane >> 2, tq = lane & 3;
    const int wrow = wm * (MT * 16);
    const int nch = K / 32;

    issue_chunk<MT>(A, lda, B, ldb, stg, 0); cp_commit();
    if (nch > 1) issue_chunk<MT>(A, lda, B, ldb, stg + STAGE, 32);
    cp_commit();
    if (nch > 2) issue_chunk<MT>(A, lda, B, ldb, stg + 2 * STAGE, 64);
    cp_commit();

    for (int i = 0; i < nch; i++) {
        if (i + 3 < nch)
            issue_chunk<MT>(A, lda, B, ldb, stg + ((i + 3) & 3) * STAGE, (i + 3) * 32);
        cp_commit();
        cp_wait<3>();
        __syncthreads();
        const unsigned* AsU = (const unsigned*)(stg + (i & 3) * STAGE);
        const unsigned* BsU = AsU + MT * 32 * 20;
        #pragma unroll
        for (int j = 0; j < 2; j++) {         // two k16 steps per 32-K chunk
            unsigned a[MT][4];
            #pragma unroll
            for (int mi = 0; mi < MT; mi++) {
                int rb = (wrow + mi * 16 + g) * 20 + j * 8 + tq;
                a[mi][0] = AsU[rb];
                a[mi][1] = AsU[rb + 8 * 20];
                a[mi][2] = AsU[rb + 4];
                a[mi][3] = AsU[rb + 8 * 20 + 4];
            }
            unsigned b[4][2];
            #pragma unroll
            for (int ni = 0; ni < 4; ni++) {
                int cb = (wn * 32 + ni * 8 + g) * 20 + j * 8 + tq;
                b[ni][0] = BsU[cb];
                b[ni][1] = BsU[cb + 4];
            }
            #pragma unroll
            for (int mi = 0; mi < MT; mi++)
                #pragma unroll
                for (int ni = 0; ni < 4; ni++)
                    mma16(c[mi][ni], a[mi][0], a[mi][1], a[mi][2], a[mi][3], b[ni][0], b[ni][1]);
        }
        __syncthreads();
    }
}

// ---------------- fused LSTM cell epilogue (c-state in registers, h stored fp16) -------
template<int MT>
__device__ __forceinline__ void cell_epi(
    float c[MT][4][4], int row0, int col0, int H,
    const float* zS, const float* bS, const float* w5S,
    const float* __restrict__ sPtr, int xt,
    __half* __restrict__ hnext, float* cst)
{
    const int tid = threadIdx.x, lane = tid & 31, warp = tid >> 5;
    const int wm = warp >> 2, wn = warp & 3, g = lane >> 2, q = lane & 3;
    const bool hi = (q & 1) != 0;
    #pragma unroll
    for (int mi = 0; mi < MT; mi++) {
        int rowt = wm * (MT * 16) + mi * 16 + g + (hi ? 8 : 0);
        int row = row0 + rowt;
        float xr[5];
        if (xt < 0) { xr[0] = 0.f; xr[1] = 0.f; xr[2] = 1.f; xr[3] = 0.f; xr[4] = 0.f; }
        else {
            const float* xp = sPtr + ((size_t)row * Tv + xt) * PTc;
            #pragma unroll
            for (int k = 0; k < 5; k++) xr[k] = xp[k];
        }
        #pragma unroll
        for (int ni = 0; ni < 4; ni++) {
            float d0 = __shfl_xor_sync(0xffffffffu, c[mi][ni][0], 1);
            float d1 = __shfl_xor_sync(0xffffffffu, c[mi][ni][1], 1);
            float d2 = __shfl_xor_sync(0xffffffffu, c[mi][ni][2], 1);
            float d3 = __shfl_xor_sync(0xffffffffu, c[mi][ni][3], 1);
            float gi, gf, gg, go;
            if (!hi) { gi = c[mi][ni][0]; gf = c[mi][ni][1]; gg = d0; go = d1; }
            else     { gi = d2;           gf = d3;           gg = c[mi][ni][2]; go = c[mi][ni][3]; }
            int lc = wn * 32 + ni * 8 + (q >> 1) * 4;
            if (zS) {
                const float* zp = zS + rowt * 129 + lc;
                gi += zp[0]; gf += zp[1]; gg += zp[2]; go += zp[3];
            } else {
                gi += bS[lc]; gf += bS[lc + 1]; gg += bS[lc + 2]; go += bS[lc + 3];
            }
            const float* w5 = w5S + lc * 5;
            #pragma unroll
            for (int k = 0; k < 5; k++) {
                gi += xr[k] * w5[k];
                gf += xr[k] * w5[5 + k];
                gg += xr[k] * w5[10 + k];
                go += xr[k] * w5[15 + k];
            }
            float cc = sigf(gf) * cst[mi * 4 + ni] + sigf(gi) * tanh_f(gg);
            cst[mi * 4 + ni] = cc;
            hnext[(size_t)row * H + ((col0 + lc) >> 2)] = __float2half(sigf(go) * tanh_f(cc));
        }
    }
}

// ---------------- y epilogue ----------------
__device__ __forceinline__ void y_epi(
    float c[4][4][4], int row0, int tstep,
    const float* __restrict__ bout, float* __restrict__ out,
    float* ys /*64*128*/, float* wsum)
{
    const int tid = threadIdx.x, lane = tid & 31, warp = tid >> 5;
    const int wm = warp >> 2, wn = warp & 3, g = lane >> 2, q = lane & 3;
    for (int half = 0; half < 2; half++) {
        if (wm == half) {
            #pragma unroll
            for (int mi = 0; mi < 4; mi++)
                #pragma unroll
                for (int ni = 0; ni < 4; ni++)
                    #pragma unroll
                    for (int cid = 0; cid < 4; cid++) {
                        int col = wn * 32 + ni * 8 + 2 * q + (cid & 1);
                        if (col < OUTC) {
                            int r = mi * 16 + g + ((cid >= 2) ? 8 : 0);
                            ys[r * 128 + col] = c[mi][ni][cid] + bout[col];
                        }
                    }
        }
        __syncthreads();
        float qacc = 0.f;
        for (int rr = 0; rr < 8; rr++) {
            int r = warp * 8 + rr;
            int brow = row0 + half * 64 + r;
            float* orow = out + ((size_t)tstep * Bv + brow) * OUTC;
            float v = (lane < 20) ? ys[r * 128 + lane * 6] : -3.0e38f;
            float m = wmax32(v);
            float e = (lane < 20) ? __expf(v - m) : 0.f;
            float ss = wsum32(e);
            if (lane < 20) {
                orow[lane]       = e / ss;
                orow[20 + lane]  = ys[r * 128 + lane * 6 + 1];
                orow[40 + lane]  = ys[r * 128 + lane * 6 + 2];
                orow[60 + lane]  = __expf(ys[r * 128 + lane * 6 + 3]);
                orow[80 + lane]  = __expf(ys[r * 128 + lane * 6 + 4]);
                orow[100 + lane] = tanh_f(ys[r * 128 + lane * 6 + 5]);
            } else if (lane < 23) {
                float eq = __expf(ys[r * 128 + 120 + lane - 20]);
                orow[120 + lane - 20] = eq;   // normalized later by qknorm
                qacc += eq;
            }
        }
        float qs = wsum32(qacc);
        if (lane == 0) wsum[warp] = qs;
        __syncthreads();
        if (tid == 0) {
            float tot = 0.f;
            #pragma unroll
            for (int i = 0; i < 8; i++) tot += wsum[i];
            d_qpart[tstep * 16 + ((row0 + half * 64) >> 6)] = tot;
        }
        __syncthreads();
    }
}

__device__ __forceinline__ void qknorm(float* __restrict__ out, int t) {
    float tot = 0.f;
    #pragma unroll
    for (int i = 0; i < 16; i++) tot += d_qpart[t * 16 + i];
    float inv = 1.f / tot;
    for (int idx = blockIdx.x * blockDim.x + threadIdx.x; idx < Bv * 3; idx += gridDim.x * blockDim.x)
        out[((size_t)t * Bv + (idx / 3)) * OUTC + 120 + (idx % 3)] *= inv;
}

// ---------------- kernels ----------------
__global__ void reset_k() {
    int i = threadIdx.x;
    if (i < 128) g_flagsE[i] = 0;
    if (i < 136) g_flagsD[i] = 0;
}

__global__ void prep_k(const float* __restrict__ eWihF, const float* __restrict__ eWhhF,
                       const float* __restrict__ ebF,  const float* __restrict__ eWihB,
                       const float* __restrict__ ebB,  const float* __restrict__ dWih,
                       const float* __restrict__ dWhh, const float* __restrict__ db,
                       const float* __restrict__ Wmu,  const float* __restrict__ bmu,
                       const float* __restrict__ Wsig, const float* __restrict__ bsig,
                       const float* __restrict__ Wh0,  const float* __restrict__ Wout,
                       const float* __restrict__ s)
{
    int gt = blockIdx.x * blockDim.x + threadIdx.x;
    int gs = gridDim.x * blockDim.x;
    for (int i = gt; i < 4 * DH * DH; i += gs) {
        int n = i / DH, k = i - n * DH, j = n >> 2, g4 = n & 3;
        d_WhhDh[i] = __float2half(dWhh[(size_t)(g4 * DH + j) * DH + k]);
    }
    for (int i = gt; i < 4 * DH * PTc; i += gs) {
        int n = i / PTc, k = i - n * PTc, j = n >> 2, g4 = n & 3;
        d_WihS[i] = dWih[(size_t)(g4 * DH + j) * (PTc + ZL) + k];
    }
    for (int i = gt; i < ZL * 4 * DH; i += gs) {
        int k = i / (4 * DH), n = i - k * (4 * DH), j = n >> 2, g4 = n & 3;
        d_WzT[i] = dWih[(size_t)(g4 * DH + j) * (PTc + ZL) + PTc + k];
    }
    for (int i = gt; i < 4 * DH; i += gs) {
        int j = i >> 2, g4 = i & 3;
        d_bDi[i] = db[g4 * DH + j];
    }
    for (int i = gt; i < 4 * EH * EH; i += gs) {
        int n = i / EH, k = i - n * EH, j = n >> 2, g4 = n & 3;
        d_WhhFh[i] = __float2half(eWhhF[(size_t)(g4 * EH + j) * EH + k]);
    }
    for (int i = gt; i < 4 * EH * PTc; i += gs) {
        int n = i / PTc, k = i - n * PTc, j = n >> 2, g4 = n & 3;
        d_WihF[i] = eWihF[(g4 * EH + j) * PTc + k];
    }
    for (int i = gt; i < 4 * EH; i += gs) {
        int j = i >> 2, g4 = i & 3;
        d_bF[i] = ebF[g4 * EH + j];
    }
    for (int i = gt; i < 128 * DH; i += gs) {
        int n = i / DH, k = i - n * DH;
        d_Wouth[i] = __float2half((n < OUTC) ? Wout[(size_t)n * DH + k] : 0.f);
    }
    for (int i = gt; i < 512 * 256; i += gs) {
        int k = i >> 8, j = i & 255;
        d_WvaeT[i] = (j < ZL) ? Wmu[(size_t)j * 512 + k] : Wsig[(size_t)(j - ZL) * 512 + k];
    }
    for (int i = gt; i < 2 * ZL; i += gs) d_bvae[i] = (i < ZL) ? bmu[i] : bsig[i - ZL];
    for (int i = gt; i < ZL * DH; i += gs) {
        int k = i / DH, n = i - k * DH;
        d_Wh0T[i] = Wh0[(size_t)n * ZL + k];
    }
    for (int i = gt; i < Bv * EH; i += gs) d_hEh[0][i] = __float2half(0.f);
    for (int i = gt; i < Bv * EH; i += gs) {   // backward enc LSTM = 1 step
        int b = i / EH, j = i - (i / EH) * EH;
        const float* xp = s + ((size_t)b * Tv + (Tv - 1)) * PTc;
        float gv[4];
        #pragma unroll
        for (int g = 0; g < 4; g++) {
            float a = ebB[g * EH + j];
            #pragma unroll
            for (int k = 0; k < 5; k++) a += eWihB[(size_t)(g * EH + j) * PTc + k] * xp[k];
            gv[g] = a;
        }
        float c = sigf(gv[0]) * tanh_f(gv[2]);
        d_hback[i] = sigf(gv[3]) * tanh_f(c);
    }
}

// encoder: 128 blocks = 16 row-tiles(64) x 8 col-tiles(128), K=256
#define ENC_STGH ((64 + 128) * 40)
#define ENC_SMB  (4 * ENC_STGH * 2 + 2560 + 512)
__global__ void __launch_bounds__(256, 1) enc_kernel(const float* __restrict__ s) {
    extern __shared__ __align__(16) char dsm[];
    const int tid = threadIdx.x, bid = blockIdx.x;
    int row0 = (bid >> 3) * 64, col0 = (bid & 7) * 128;
    __half* stg = (__half*)dsm;
    float* w5S = (float*)(dsm + 4 * ENC_STGH * 2);
    float* bS  = w5S + 640;
    for (int i = tid; i < 128 * 5; i += 256) w5S[i] = d_WihF[(size_t)col0 * 5 + i];
    for (int i = tid; i < 128; i += 256) bS[i] = d_bF[col0 + i];
    __syncthreads();
    float cst[8];
    #pragma unroll
    for (int i = 0; i < 8; i++) cst[i] = 0.f;
    for (int t = 0; t < Tv; t++) {
        const __half* hprev = d_hEh[t & 1];
        __half* hnext = d_hEh[(t + 1) & 1];
        float c[2][4][4] = {};
        mma_pipe<2>(hprev + (size_t)row0 * EH, EH, EH,
                    d_WhhFh + (size_t)col0 * EH, EH, stg, c);
        cell_epi<2>(c, row0, col0, EH, nullptr, bS, w5S, s, t, hnext, cst);
        gsync(g_flagsE, 128, t + 1);
    }
}

__global__ void vae1_k() {   // 256 blocks x 256 thr, 4 rows each
    __shared__ float h[4][512];
    int b0 = blockIdx.x * 4, tid = threadIdx.x;
    for (int i = tid; i < 4 * 512; i += 256) {
        int r = i >> 9, k = i & 511;
        h[r][k] = (k < 256) ? __half2float(d_hEh[0][(size_t)(b0 + r) * 256 + k])
                            : d_hback[(size_t)(b0 + r) * 256 + k - 256];
    }
    __syncthreads();
    float acc[4];
    #pragma unroll
    for (int r = 0; r < 4; r++) acc[r] = d_bvae[tid];
    for (int k = 0; k < 512; k++) {
        float w = d_WvaeT[k * 256 + tid];
        #pragma unroll
        for (int r = 0; r < 4; r++) acc[r] += h[r][k] * w;
    }
    #pragma unroll
    for (int r = 0; r < 4; r++) d_mups[(size_t)(b0 + r) * 256 + tid] = acc[r];
}

__global__ void zk(const float* __restrict__ eps) {
    int i = blockIdx.x * blockDim.x + threadIdx.x;
    if (i < Bv * ZL) {
        int b = i >> 7, j = i & 127;
        d_z[i] = d_mups[(size_t)b * 256 + j]
               + __expf(0.5f * d_mups[(size_t)b * 256 + 128 + j]) * eps[i];
    }
}

__global__ void vae2a_k(const float* __restrict__ bh0) {   // 256 blocks x 512 thr
    __shared__ float z4[4][128];
    int b0 = blockIdx.x * 4, tid = threadIdx.x;
    for (int i = tid; i < 4 * 128; i += 512) z4[i >> 7][i & 127] = d_z[(size_t)b0 * 128 + i];
    __syncthreads();
    float acc[4];
    #pragma unroll
    for (int r = 0; r < 4; r++) acc[r] = bh0[tid];
    for (int k = 0; k < 128; k++) {
        float w = d_Wh0T[k * 512 + tid];
        #pragma unroll
        for (int r = 0; r < 4; r++) acc[r] += z4[r][k] * w;
    }
    #pragma unroll
    for (int r = 0; r < 4; r++)
        d_hDh[0][(size_t)(b0 + r) * 512 + tid] = __float2half(tanh_f(acc[r]));
}

__global__ void vae2b_k() {   // 512 blocks x 256 thr
    __shared__ float z2[2][128];
    int b0 = blockIdx.x * 2, tid = threadIdx.x;
    for (int i = tid; i < 2 * 128; i += 256) z2[i >> 7][i & 127] = d_z[(size_t)b0 * 128 + i];
    __syncthreads();
    float acc[16];
    #pragma unroll
    for (int i = 0; i < 16; i++) acc[i] = 0.f;
    for (int k = 0; k < 128; k++) {
        float z0 = z2[0][k], z1 = z2[1][k];
        #pragma unroll
        for (int m = 0; m < 8; m++) {
            float w = d_WzT[(size_t)k * 2048 + tid + 256 * m];
            acc[m] += z0 * w;
            acc[8 + m] += z1 * w;
        }
    }
    #pragma unroll
    for (int m = 0; m < 8; m++) {
        float bb = d_bDi[tid + 256 * m];
        d_zproj[(size_t)b0 * 2048 + tid + 256 * m] = acc[m] + bb;
        d_zproj[(size_t)(b0 + 1) * 2048 + tid + 256 * m] = acc[8 + m] + bb;
    }
}

// decoder: 136 blocks = 128 gate tiles (8 row x 16 col) + 8 y tiles, K=512
#define DEC_STGH ((128 + 128) * 40)
#define DEC_SMB  (4 * DEC_STGH * 2 + 128 * 129 * 4 + 2560 + 32)
__global__ void __launch_bounds__(256, 1) dec_kernel(const float* __restrict__ s,
    const float* __restrict__ bout, float* __restrict__ out)
{
    extern __shared__ __align__(16) char dsm[];
    const int tid = threadIdx.x, bid = blockIdx.x;
    __half* stg = (__half*)dsm;
    float* zS   = (float*)(dsm + 4 * DEC_STGH * 2);
    float* w5S  = zS + 128 * 129;
    float* wsum = w5S + 640;
    float* ys   = (float*)dsm;   // overlays staging for y blocks (after MMA drains)
    float cst[16];
    #pragma unroll
    for (int i = 0; i < 16; i++) cst[i] = 0.f;
    int row0, col0 = 0;
    if (bid < 128) {
        row0 = (bid >> 4) * 128; col0 = (bid & 15) * 128;
        for (int i = tid; i < 128 * 128; i += 256) {
            int r = i >> 7, c = i & 127;
            zS[r * 129 + c] = d_zproj[(size_t)(row0 + r) * 2048 + col0 + c];
        }
        for (int i = tid; i < 128 * 5; i += 256) w5S[i] = d_WihS[(size_t)col0 * 5 + i];
        __syncthreads();
    } else {
        row0 = (bid - 128) * 128;
    }
    for (int t = 0; t < Tv; t++) {
        const __half* hprev = d_hDh[t & 1];
        if (t >= 2) qknorm(out, t - 2);
        if (bid < 128) {
            __half* hnext = d_hDh[(t + 1) & 1];
            float c[4][4][4] = {};
            mma_pipe<4>(hprev + (size_t)row0 * DH, DH, DH,
                        d_WhhDh + (size_t)col0 * DH, DH, stg, c);
            cell_epi<4>(c, row0, col0, DH, zS, nullptr, w5S, s, t - 1, hnext, cst);
        } else if (t >= 1) {
            float c[4][4][4] = {};
            mma_pipe<4>(hprev + (size_t)row0 * DH, DH, DH, d_Wouth, DH, stg, c);
            y_epi(c, row0, t - 1, bout, out, ys, wsum);
        }
        gsync(g_flagsD, 136, t + 1);
    }
    qknorm(out, 254);
    if (bid >= 128) {
        float c[4][4][4] = {};
        mma_pipe<4>(d_hDh[0] + (size_t)row0 * DH, DH, DH, d_Wouth, DH, stg, c);
        y_epi(c, row0, 255, bout, out, ys, wsum);
    }
    gsync(g_flagsD, 136, Tv + 1);
    qknorm(out, 255);
}

// ---------------- launch ----------------
extern "C" void kernel_launch(void* const* d_in, const int* in_sizes, int n_in,
                              void* d_out, int out_size)
{
    const float* s     = (const float*)d_in[0];
    const float* eps   = (const float*)d_in[1];
    const float* eWihF = (const float*)d_in[2];
    const float* eWhhF = (const float*)d_in[3];
    const float* ebF   = (const float*)d_in[4];
    const float* eWihB = (const float*)d_in[5];
    // d_in[6] = enc_Whh_b : unused (backward LSTM output only needs its first step)
    const float* ebB   = (const float*)d_in[7];
    const float* Wmu   = (const float*)d_in[8];
    const float* bmu   = (const float*)d_in[9];
    const float* Wsig  = (const float*)d_in[10];
    const float* bsig  = (const float*)d_in[11];
    const float* Wh0   = (const float*)d_in[12];
    const float* bh0   = (const float*)d_in[13];
    const float* dWih  = (const float*)d_in[14];
    const float* dWhh  = (const float*)d_in[15];
    const float* db    = (const float*)d_in[16];
    const float* Wout  = (const float*)d_in[17];
    const float* bout  = (const float*)d_in[18];
    float* out = (float*)d_out;

    static int inited = 0;
    if (!inited) {
        cudaFuncSetAttribute(enc_kernel, cudaFuncAttributeMaxDynamicSharedMemorySize, ENC_SMB);
        cudaFuncSetAttribute(dec_kernel, cudaFuncAttributeMaxDynamicSharedMemorySize, DEC_SMB);
        inited = 1;
    }

    reset_k<<<1, 256>>>();
    prep_k<<<2048, 256>>>(eWihF, eWhhF, ebF, eWihB, ebB, dWih, dWhh, db,
                          Wmu, bmu, Wsig, bsig, Wh0, Wout, s);
    enc_kernel<<<128, 256, ENC_SMB>>>(s);
    vae1_k<<<256, 256>>>();
    zk<<<(Bv * ZL + 255) / 256, 256>>>(eps);
    vae2a_k<<<256, 512>>>(bh0);
    vae2b_k<<<512, 256>>>();
    dec_kernel<<<136, 256, DEC_SMB>>>(s, bout, out);
}